// round 8
// baseline (speedup 1.0000x reference)
#include <cuda_runtime.h>
#include <math.h>

#define NMAX 393216   // 768 * 512 upper bound on total nodes
#define AT_S 134      // transposed tile stride (even for 8B ull loads)
#define AGG_S 68      // agg row stride (pad to avoid bank conflicts)

typedef unsigned long long ull;

// scratch (allocation-free rule: device globals)
__device__ float g_bufA[NMAX * 64];
__device__ float g_bufB[NMAX * 64];
__device__ float g_gA[NMAX * 64];
__device__ float g_gB[NMAX * 64];
__device__ float g_embv[NMAX * 32];
__device__ float g_logit[NMAX];

// dynamic smem layout (bytes)
#define OFF_WS   34304                    // at = 64*134*4
#define OFF_AGG  (OFF_WS + 16384)         // ws[4096]
#define OFF_WES  (OFF_AGG + 34816)        // agg = 128*68*4
#define OFF_BS   (OFF_WES + 1024)         // wes[256]
#define SM_LAYER (OFF_BS + 256)           // bs[64]
#define SM_L2    (SM_LAYER + 128)         // + bos[32]
#define SM_IN_G  (OFF_AGG + 4608 + 256)   // xs[128][9] + bs[64]

// packed fp32x2 helpers (Blackwell)
#define FFMA2(d, a, b) asm("fma.rn.f32x2 %0, %1, %2, %0;" : "+l"(d) : "l"(a), "l"(b))
#define PACKF2(d, x)   asm("mov.b64 %0, {%1, %1};" : "=l"(d) : "f"(x))
#define UNPACK2(lo, hi, p) asm("mov.b64 {%0, %1}, %2;" : "=f"(lo), "=f"(hi) : "l"(p))

// ---- 128x64x64 mma (by 128 threads): 8 rows x 8 cols/thread, rowpair f32x2 ----
__device__ __forceinline__ void mma8(const float (*at)[AT_S], const float* __restrict__ ws,
                                     int r0, int c0, ull acc[4][8]) {
#pragma unroll
    for (int p = 0; p < 4; p++)
#pragma unroll
        for (int c = 0; c < 8; c++) acc[p][c] = 0ULL;
#pragma unroll 8
    for (int k = 0; k < 64; k++) {
        const ull* ap = (const ull*)&at[k][r0];
        ull a0 = ap[0], a1 = ap[1], a2 = ap[2], a3 = ap[3];
        const float4* wp = (const float4*)&ws[k * 64 + c0];
        float4 wA = wp[0], wB = wp[1];
        ull w0, w1, w2, w3, w4, w5, w6, w7;
        PACKF2(w0, wA.x); PACKF2(w1, wA.y); PACKF2(w2, wA.z); PACKF2(w3, wA.w);
        PACKF2(w4, wB.x); PACKF2(w5, wB.y); PACKF2(w6, wB.z); PACKF2(w7, wB.w);
        FFMA2(acc[0][0], a0, w0); FFMA2(acc[0][1], a0, w1);
        FFMA2(acc[0][2], a0, w2); FFMA2(acc[0][3], a0, w3);
        FFMA2(acc[0][4], a0, w4); FFMA2(acc[0][5], a0, w5);
        FFMA2(acc[0][6], a0, w6); FFMA2(acc[0][7], a0, w7);
        FFMA2(acc[1][0], a1, w0); FFMA2(acc[1][1], a1, w1);
        FFMA2(acc[1][2], a1, w2); FFMA2(acc[1][3], a1, w3);
        FFMA2(acc[1][4], a1, w4); FFMA2(acc[1][5], a1, w5);
        FFMA2(acc[1][6], a1, w6); FFMA2(acc[1][7], a1, w7);
        FFMA2(acc[2][0], a2, w0); FFMA2(acc[2][1], a2, w1);
        FFMA2(acc[2][2], a2, w2); FFMA2(acc[2][3], a2, w3);
        FFMA2(acc[2][4], a2, w4); FFMA2(acc[2][5], a2, w5);
        FFMA2(acc[2][6], a2, w6); FFMA2(acc[2][7], a2, w7);
        FFMA2(acc[3][0], a3, w0); FFMA2(acc[3][1], a3, w1);
        FFMA2(acc[3][2], a3, w2); FFMA2(acc[3][3], a3, w3);
        FFMA2(acc[3][4], a3, w4); FFMA2(acc[3][5], a3, w5);
        FFMA2(acc[3][6], a3, w6); FFMA2(acc[3][7], a3, w7);
    }
}

// ---- 128x64x64 mma by 256 threads: 8 rows x 4 cols/thread ----
__device__ __forceinline__ void mma64_4(const float (*at)[AT_S], const float* __restrict__ ws,
                                        int r0, int c0, ull acc[4][4]) {
#pragma unroll
    for (int p = 0; p < 4; p++)
#pragma unroll
        for (int c = 0; c < 4; c++) acc[p][c] = 0ULL;
#pragma unroll 8
    for (int k = 0; k < 64; k++) {
        const ull* ap = (const ull*)&at[k][r0];
        ull a0 = ap[0], a1 = ap[1], a2 = ap[2], a3 = ap[3];
        float4 wA = *(const float4*)&ws[k * 64 + c0];
        ull w0, w1, w2, w3;
        PACKF2(w0, wA.x); PACKF2(w1, wA.y); PACKF2(w2, wA.z); PACKF2(w3, wA.w);
        FFMA2(acc[0][0], a0, w0); FFMA2(acc[0][1], a0, w1);
        FFMA2(acc[0][2], a0, w2); FFMA2(acc[0][3], a0, w3);
        FFMA2(acc[1][0], a1, w0); FFMA2(acc[1][1], a1, w1);
        FFMA2(acc[1][2], a1, w2); FFMA2(acc[1][3], a1, w3);
        FFMA2(acc[2][0], a2, w0); FFMA2(acc[2][1], a2, w1);
        FFMA2(acc[2][2], a2, w2); FFMA2(acc[2][3], a2, w3);
        FFMA2(acc[3][0], a3, w0); FFMA2(acc[3][1], a3, w1);
        FFMA2(acc[3][2], a3, w2); FFMA2(acc[3][3], a3, w3);
    }
}

// ---- 128x32x64 mma by 256 threads: 8 rows x 2 cols/thread (ws stride 32) ----
__device__ __forceinline__ void mma32_2(const float (*at)[AT_S], const float* __restrict__ ws,
                                        int r0, int c0, ull acc[4][2]) {
#pragma unroll
    for (int p = 0; p < 4; p++)
#pragma unroll
        for (int c = 0; c < 2; c++) acc[p][c] = 0ULL;
#pragma unroll 8
    for (int k = 0; k < 64; k++) {
        const ull* ap = (const ull*)&at[k][r0];
        ull a0 = ap[0], a1 = ap[1], a2 = ap[2], a3 = ap[3];
        float2 wA = *(const float2*)&ws[k * 32 + c0];
        ull w0, w1;
        PACKF2(w0, wA.x); PACKF2(w1, wA.y);
        FFMA2(acc[0][0], a0, w0); FFMA2(acc[0][1], a0, w1);
        FFMA2(acc[1][0], a1, w0); FFMA2(acc[1][1], a1, w1);
        FFMA2(acc[2][0], a2, w0); FFMA2(acc[2][1], a2, w1);
        FFMA2(acc[3][0], a3, w0); FFMA2(acc[3][1], a3, w1);
    }
}

// ---- stage a 128x64 tile transposed into at[k][row], 256 threads ----
__device__ __forceinline__ void stage_tile(const float* __restrict__ A, int i0, int N,
                                           float (*at)[AT_S], int tid) {
    int lrow = tid >> 1;
    int q0 = (tid & 1) * 8;
    int i = i0 + lrow;
    const float4* A4 = (const float4*)A;
#pragma unroll
    for (int q = 0; q < 8; q++) {
        float4 v = (i < N) ? A4[(size_t)i * 16 + q0 + q] : make_float4(0.f, 0.f, 0.f, 0.f);
        int kb = (q0 + q) * 4;
        at[kb + 0][lrow] = v.x;
        at[kb + 1][lrow] = v.y;
        at[kb + 2][lrow] = v.z;
        at[kb + 3][lrow] = v.w;
    }
}

// ---- gather warps: agg[row][q0..q0+15] = sum_e relu(G[src_e] + ea_e @ wedge) ----
__device__ __forceinline__ void gather_agg(const float* __restrict__ G,
                                           const int* __restrict__ src,
                                           const float* __restrict__ ea,
                                           const float* __restrict__ wes,
                                           float* __restrict__ agg,
                                           int i0, int N, int gtid) {
    int qr = gtid >> 2;
    int q0 = (gtid & 3) * 16;
    float4 wr[4][4];
#pragma unroll
    for (int d = 0; d < 4; d++)
#pragma unroll
        for (int c = 0; c < 4; c++) wr[d][c] = *(const float4*)&wes[d * 64 + q0 + c * 4];
#pragma unroll
    for (int pass = 0; pass < 4; pass++) {
        int row = pass * 32 + qr;
        int i = i0 + row;
        float4 a4[4];
#pragma unroll
        for (int c = 0; c < 4; c++) a4[c] = make_float4(0.f, 0.f, 0.f, 0.f);
        if (i < N) {
            int4 s4 = *(const int4*)&src[4 * i];
            int ss[4] = {s4.x, s4.y, s4.z, s4.w};
#pragma unroll
            for (int e = 0; e < 4; e++) {
                const float4* gp = (const float4*)&G[(size_t)ss[e] * 64 + q0];
                float4 e4 = *(const float4*)&ea[(size_t)16 * i + 4 * e];
#pragma unroll
                for (int c = 0; c < 4; c++) {
                    float4 m = gp[c];
                    m.x += e4.x * wr[0][c].x + e4.y * wr[1][c].x + e4.z * wr[2][c].x + e4.w * wr[3][c].x;
                    m.y += e4.x * wr[0][c].y + e4.y * wr[1][c].y + e4.z * wr[2][c].y + e4.w * wr[3][c].y;
                    m.z += e4.x * wr[0][c].z + e4.y * wr[1][c].z + e4.z * wr[2][c].z + e4.w * wr[3][c].z;
                    m.w += e4.x * wr[0][c].w + e4.y * wr[1][c].w + e4.z * wr[2][c].w + e4.w * wr[3][c].w;
                    a4[c].x += fmaxf(m.x, 0.f); a4[c].y += fmaxf(m.y, 0.f);
                    a4[c].z += fmaxf(m.z, 0.f); a4[c].w += fmaxf(m.w, 0.f);
                }
            }
        }
#pragma unroll
        for (int c = 0; c < 4; c++)
            *(float4*)&agg[row * AGG_S + q0 + c * 4] = a4[c];
    }
}

// =============== k_in_g: h0 = relu(x@w_in+b); G0 = h0 @ w_nb[0] ===============
__global__ void __launch_bounds__(256, 2) k_in_g(const float* __restrict__ x,
                                                 const float* __restrict__ w_in,
                                                 const float* __restrict__ b_in,
                                                 const float* __restrict__ wnb0,
                                                 float* __restrict__ H0,
                                                 float* __restrict__ G0, int N) {
    extern __shared__ __align__(16) char sm[];
    float (*at)[AT_S] = (float (*)[AT_S])sm;
    float* ws = (float*)(sm + OFF_WS);
    float (*xs)[9] = (float (*)[9])(sm + OFF_AGG);
    float* bs = (float*)(sm + OFF_AGG + 4608);
    int tid = threadIdx.x;
    int i0 = blockIdx.x * 128;
    for (int t = tid; t < 512; t += 256) ws[t] = w_in[t];
    if (tid < 64) bs[tid] = b_in[tid];
    if (tid < 128) {
        int i = i0 + tid;
        float4 v0, v1;
        if (i < N) { v0 = ((const float4*)x)[i * 2]; v1 = ((const float4*)x)[i * 2 + 1]; }
        else { v0 = make_float4(0.f, 0.f, 0.f, 0.f); v1 = v0; }
        xs[tid][0] = v0.x; xs[tid][1] = v0.y; xs[tid][2] = v0.z; xs[tid][3] = v0.w;
        xs[tid][4] = v1.x; xs[tid][5] = v1.y; xs[tid][6] = v1.z; xs[tid][7] = v1.w;
    }
    __syncthreads();
    // input GEMM: 256 threads, 4 rows x 8 cols each
    int tr = tid >> 3, tc = tid & 7;   // tr 0..31
    int r0i = tr * 4, c0 = tc * 8;
    float acc[4][8];
#pragma unroll
    for (int r = 0; r < 4; r++)
#pragma unroll
        for (int c = 0; c < 8; c++) acc[r][c] = bs[c0 + c];
#pragma unroll
    for (int k = 0; k < 8; k++) {
        float w8[8];
#pragma unroll
        for (int c = 0; c < 8; c++) w8[c] = ws[k * 64 + c0 + c];
#pragma unroll
        for (int r = 0; r < 4; r++) {
            float a = xs[r0i + r][k];
#pragma unroll
            for (int c = 0; c < 8; c++) acc[r][c] += a * w8[c];
        }
    }
#pragma unroll
    for (int r = 0; r < 4; r++) {
        int row = r0i + r;
        int i = i0 + row;
#pragma unroll
        for (int c = 0; c < 8; c++) acc[r][c] = fmaxf(acc[r][c], 0.f);
        if (i < N) {
            *(float4*)&H0[(size_t)i * 64 + c0] = make_float4(acc[r][0], acc[r][1], acc[r][2], acc[r][3]);
            *(float4*)&H0[(size_t)i * 64 + c0 + 4] = make_float4(acc[r][4], acc[r][5], acc[r][6], acc[r][7]);
        }
#pragma unroll
        for (int c = 0; c < 8; c++) at[c0 + c][row] = acc[r][c];
    }
    __syncthreads();
    for (int t = tid; t < 4096; t += 256) ws[t] = wnb0[t];
    __syncthreads();
    // G0 GEMM: 256 threads, 8 rows x 4 cols each
    int r0 = (tid >> 4) * 8, c04 = (tid & 15) * 4;
    ull acc2[4][4];
    mma64_4(at, ws, r0, c04, acc2);
#pragma unroll
    for (int p = 0; p < 4; p++) {
        float lo[4], hi[4];
#pragma unroll
        for (int c = 0; c < 4; c++) UNPACK2(lo[c], hi[c], acc2[p][c]);
        int ia = i0 + r0 + 2 * p;
        if (ia < N)
            *(float4*)&G0[(size_t)ia * 64 + c04] = make_float4(lo[0], lo[1], lo[2], lo[3]);
        if (ia + 1 < N)
            *(float4*)&G0[(size_t)(ia + 1) * 64 + c04] = make_float4(hi[0], hi[1], hi[2], hi[3]);
    }
}

// === fused layer: warps 0-3 GEMM1 | warps 4-7 gather; then all GEMM2 ===
// relies on dst == repeat(arange(N),4): node i's edges are [4i, 4i+4)
__global__ void __launch_bounds__(256, 2) k_layer_f(const float* __restrict__ H,
                                                    const float* __restrict__ G,
                                                    const float* __restrict__ wself,
                                                    const float* __restrict__ wedge,
                                                    const float* __restrict__ bl,
                                                    const int* __restrict__ src,
                                                    const float* __restrict__ ea,
                                                    const float* __restrict__ wnb_next,
                                                    float* __restrict__ Hout,
                                                    float* __restrict__ Gnext, int N) {
    extern __shared__ __align__(16) char sm[];
    float (*at)[AT_S] = (float (*)[AT_S])sm;
    float* ws = (float*)(sm + OFF_WS);
    float* agg = (float*)(sm + OFF_AGG);
    float* wes = (float*)(sm + OFF_WES);
    float* bs = (float*)(sm + OFF_BS);
    int tid = threadIdx.x;
    int i0 = blockIdx.x * 128;
    for (int t = tid; t < 4096; t += 256) ws[t] = wself[t];
    if (tid < 256) wes[tid] = wedge[tid];
    if (tid < 64) bs[tid] = bl[tid];
    stage_tile(H, i0, N, at, tid);
    __syncthreads();

    ull acc[4][8];
    int r0g = (tid & 15) * 8, c0g = ((tid >> 4) & 7) * 8;  // only used by tid<128
    if (tid < 128) {
        int tr = tid >> 3, tc = tid & 7;
        r0g = tr * 8; c0g = tc * 8;
        mma8(at, ws, r0g, c0g, acc);
    } else {
        gather_agg(G, src, ea, wes, agg, i0, N, tid - 128);
    }
    __syncthreads();

    if (tid < 128) {
        // combine: h' = relu(gemm1 + agg + b); write Hout and at
#pragma unroll
        for (int p = 0; p < 4; p++) {
            float v[2][8];
#pragma unroll
            for (int c = 0; c < 8; c++) UNPACK2(v[0][c], v[1][c], acc[p][c]);
#pragma unroll
            for (int rr = 0; rr < 2; rr++) {
                int row = r0g + 2 * p + rr;
                int i = i0 + row;
                if (i < N) {
                    float4 ag0 = *(const float4*)&agg[row * AGG_S + c0g];
                    float4 ag1 = *(const float4*)&agg[row * AGG_S + c0g + 4];
                    float o[8];
                    o[0] = fmaxf(v[rr][0] + ag0.x + bs[c0g + 0], 0.f);
                    o[1] = fmaxf(v[rr][1] + ag0.y + bs[c0g + 1], 0.f);
                    o[2] = fmaxf(v[rr][2] + ag0.z + bs[c0g + 2], 0.f);
                    o[3] = fmaxf(v[rr][3] + ag0.w + bs[c0g + 3], 0.f);
                    o[4] = fmaxf(v[rr][4] + ag1.x + bs[c0g + 4], 0.f);
                    o[5] = fmaxf(v[rr][5] + ag1.y + bs[c0g + 5], 0.f);
                    o[6] = fmaxf(v[rr][6] + ag1.z + bs[c0g + 6], 0.f);
                    o[7] = fmaxf(v[rr][7] + ag1.w + bs[c0g + 7], 0.f);
                    *(float4*)&Hout[(size_t)i * 64 + c0g] = make_float4(o[0], o[1], o[2], o[3]);
                    *(float4*)&Hout[(size_t)i * 64 + c0g + 4] = make_float4(o[4], o[5], o[6], o[7]);
#pragma unroll
                    for (int c = 0; c < 8; c++) at[c0g + c][row] = o[c];
                }
            }
        }
    } else {
        int gt = tid - 128;
        for (int t = gt; t < 4096; t += 128) ws[t] = wnb_next[t];
    }
    __syncthreads();

    // GEMM2 with all 256 threads
    int r0 = (tid >> 4) * 8, c04 = (tid & 15) * 4;
    ull acc2[4][4];
    mma64_4(at, ws, r0, c04, acc2);
#pragma unroll
    for (int p = 0; p < 4; p++) {
        float lo[4], hi[4];
#pragma unroll
        for (int c = 0; c < 4; c++) UNPACK2(lo[c], hi[c], acc2[p][c]);
        int ia = i0 + r0 + 2 * p;
        if (ia < N)
            *(float4*)&Gnext[(size_t)ia * 64 + c04] = make_float4(lo[0], lo[1], lo[2], lo[3]);
        if (ia + 1 < N)
            *(float4*)&Gnext[(size_t)(ia + 1) * 64 + c04] = make_float4(hi[0], hi[1], hi[2], hi[3]);
    }
}

// === last layer: h3; emb = h3@wout + bout; logit = MLP(emb) ===
__global__ void __launch_bounds__(256, 2) k_l2(const float* __restrict__ H,
                                               const float* __restrict__ G,
                                               const float* __restrict__ wself,
                                               const float* __restrict__ wedge,
                                               const float* __restrict__ bl,
                                               const int* __restrict__ src,
                                               const float* __restrict__ ea,
                                               const float* __restrict__ wout,
                                               const float* __restrict__ bout,
                                               const float* __restrict__ law1,
                                               const float* __restrict__ lab1,
                                               const float* __restrict__ law2,
                                               const float* __restrict__ lab2,
                                               float* __restrict__ emb,
                                               float* __restrict__ logit, int N) {
    extern __shared__ __align__(16) char sm[];
    float (*at)[AT_S] = (float (*)[AT_S])sm;
    float* ws = (float*)(sm + OFF_WS);
    float* agg = (float*)(sm + OFF_AGG);
    float* wes = (float*)(sm + OFF_WES);
    float* bs = (float*)(sm + OFF_BS);
    float* bos = (float*)(sm + SM_LAYER);
    int tid = threadIdx.x;
    int i0 = blockIdx.x * 128;
    for (int t = tid; t < 4096; t += 256) ws[t] = wself[t];
    if (tid < 256) wes[tid] = wedge[tid];
    if (tid < 64) bs[tid] = bl[tid];
    if (tid < 32) bos[tid] = bout[tid];
    stage_tile(H, i0, N, at, tid);
    __syncthreads();

    ull acc[4][8];
    int r0g = 0, c0g = 0;
    if (tid < 128) {
        int tr = tid >> 3, tc = tid & 7;
        r0g = tr * 8; c0g = tc * 8;
        mma8(at, ws, r0g, c0g, acc);
    } else {
        gather_agg(G, src, ea, wes, agg, i0, N, tid - 128);
    }
    __syncthreads();

    if (tid < 128) {
#pragma unroll
        for (int p = 0; p < 4; p++) {
            float v[2][8];
#pragma unroll
            for (int c = 0; c < 8; c++) UNPACK2(v[0][c], v[1][c], acc[p][c]);
#pragma unroll
            for (int rr = 0; rr < 2; rr++) {
                int row = r0g + 2 * p + rr;
                int i = i0 + row;
                if (i < N) {
                    float4 ag0 = *(const float4*)&agg[row * AGG_S + c0g];
                    float4 ag1 = *(const float4*)&agg[row * AGG_S + c0g + 4];
                    float o[8];
                    o[0] = fmaxf(v[rr][0] + ag0.x + bs[c0g + 0], 0.f);
                    o[1] = fmaxf(v[rr][1] + ag0.y + bs[c0g + 1], 0.f);
                    o[2] = fmaxf(v[rr][2] + ag0.z + bs[c0g + 2], 0.f);
                    o[3] = fmaxf(v[rr][3] + ag0.w + bs[c0g + 3], 0.f);
                    o[4] = fmaxf(v[rr][4] + ag1.x + bs[c0g + 4], 0.f);
                    o[5] = fmaxf(v[rr][5] + ag1.y + bs[c0g + 5], 0.f);
                    o[6] = fmaxf(v[rr][6] + ag1.z + bs[c0g + 6], 0.f);
                    o[7] = fmaxf(v[rr][7] + ag1.w + bs[c0g + 7], 0.f);
#pragma unroll
                    for (int c = 0; c < 8; c++) at[c0g + c][row] = o[c];
                }
            }
        }
    } else {
        // ws: [0..2047]=wout, [2048..3071]=la_w1, [3072..3103]=la_b1, [3104..3135]=la_w2
        int gt = tid - 128;
        for (int t = gt; t < 2048; t += 128) ws[t] = wout[t];
        for (int t = gt; t < 1024; t += 128) ws[2048 + t] = law1[t];
        if (gt < 32) { ws[3072 + gt] = lab1[gt]; ws[3104 + gt] = law2[gt]; }
    }
    __syncthreads();

    // emb GEMM: 256 threads, 8 rows x 2 cols each
    int r0 = (tid >> 4) * 8, c02 = (tid & 15) * 2;
    ull acc2[4][2];
    mma32_2(at, ws, r0, c02, acc2);
    __syncthreads();  // (readers of at done; em goes in agg region anyway)

    float* em = agg;  // reuse agg region as em[row*33 + c]
#pragma unroll
    for (int p = 0; p < 4; p++) {
        float lo[2], hi[2];
        UNPACK2(lo[0], hi[0], acc2[p][0]);
        UNPACK2(lo[1], hi[1], acc2[p][1]);
        lo[0] += bos[c02]; lo[1] += bos[c02 + 1];
        hi[0] += bos[c02]; hi[1] += bos[c02 + 1];
        int rowa = r0 + 2 * p;
        int ia = i0 + rowa;
        if (ia < N)
            *(float2*)&emb[(size_t)ia * 32 + c02] = make_float2(lo[0], lo[1]);
        if (ia + 1 < N)
            *(float2*)&emb[(size_t)(ia + 1) * 32 + c02] = make_float2(hi[0], hi[1]);
        em[rowa * 33 + c02] = lo[0];
        em[rowa * 33 + c02 + 1] = lo[1];
        em[(rowa + 1) * 33 + c02] = hi[0];
        em[(rowa + 1) * 33 + c02 + 1] = hi[1];
    }
    __syncthreads();

    // per-node location logit MLP: two threads per row, split over output j
    {
        int row = tid >> 1;
        int half = tid & 1;
        int i = i0 + row;
        float vsum = 0.f;
        if (i < N) {
            float er[32];
#pragma unroll
            for (int k = 0; k < 32; k++) er[k] = em[row * 33 + k];
#pragma unroll 4
            for (int jj = 0; jj < 16; jj++) {
                int j = half * 16 + jj;
                float s = ws[3072 + j];
#pragma unroll
                for (int k = 0; k < 32; k++) s += er[k] * ws[2048 + k * 32 + j];
                vsum += fmaxf(s, 0.f) * ws[3104 + j];
            }
        }
        vsum += __shfl_xor_sync(0xffffffffu, vsum, 1);
        if (half == 0 && i < N) logit[i] = vsum + lab2[0];
    }
}

// -------- per-graph heads: one block per graph --------
__global__ void k_heads(const float* __restrict__ emb, const float* __restrict__ logit,
                        const int* __restrict__ ptr, const int* __restrict__ loc,
                        const int* __restrict__ mut,
                        const float* __restrict__ maw1, const float* __restrict__ mab1,
                        const float* __restrict__ maw2, const float* __restrict__ mab2,
                        const float* __restrict__ lcw1, const float* __restrict__ lcb1,
                        const float* __restrict__ lcw2, const float* __restrict__ lcb2,
                        const float* __restrict__ mcw1, const float* __restrict__ mcb1,
                        const float* __restrict__ mcw2, const float* __restrict__ mcb2,
                        float* __restrict__ out, int B) {
    __shared__ float ls[768];
    __shared__ float red[256];
    __shared__ float red2[256];
    __shared__ float pool[8][33];
    __shared__ float poolr[32];
    __shared__ float selr[32];
    __shared__ float hidm[32];
    int b = blockIdx.x, tid = threadIdx.x;
    int i0 = ptr[b], i1 = ptr[b + 1];
    int cnt = i1 - i0;
    for (int t = tid; t < cnt; t += 256) ls[t] = logit[i0 + t];
    int j = tid & 31, r = tid >> 5;
    float p = 0.f;
    for (int t = r; t < cnt; t += 8) p += emb[(size_t)(i0 + t) * 32 + j];
    pool[r][j] = p;
    __syncthreads();
    if (tid < 32) {
        float s = 0.f;
#pragma unroll
        for (int rr = 0; rr < 8; rr++) s += pool[rr][tid];
        poolr[tid] = s;
    }
    float m = -1e30f;
    for (int t = tid; t < cnt; t += 256) m = fmaxf(m, ls[t]);
    red[tid] = m;
    __syncthreads();
    for (int s = 128; s > 0; s >>= 1) {
        if (tid < s) red[tid] = fmaxf(red[tid], red[tid + s]);
        __syncthreads();
    }
    m = red[0];
    __syncthreads();
    float z = 0.f, sz = 0.f;
    for (int t = tid; t < cnt; t += 256) {
        float zz = ls[t] - m;
        float e = expf(zz);
        z += e; sz += e * zz;
    }
    red[tid] = z; red2[tid] = sz;
    __syncthreads();
    for (int s = 128; s > 0; s >>= 1) {
        if (tid < s) { red[tid] += red[tid + s]; red2[tid] += red2[tid + s]; }
        __syncthreads();
    }
    float Z = red[0], S = red2[0];
    float logZ = logf(Z);
    int gl = i0 + loc[b];
    if (tid < 32) selr[tid] = emb[(size_t)gl * 32 + tid];
    __syncthreads();
    if (tid < 32) {
        float h1 = mab1[tid];
#pragma unroll
        for (int k = 0; k < 32; k++) h1 += selr[k] * maw1[k * 32 + tid];
        hidm[tid] = fmaxf(h1, 0.f);
    }
    __syncthreads();
    if (tid == 0) {
        float lg[4];
        float mm = -1e30f;
#pragma unroll
        for (int q = 0; q < 4; q++) {
            float s = mab2[q];
            for (int k = 0; k < 32; k++) s += hidm[k] * maw2[k * 4 + q];
            lg[q] = s; mm = fmaxf(mm, s);
        }
        float se = 0.f;
#pragma unroll
        for (int q = 0; q < 4; q++) se += expf(lg[q] - mm);
        float lse = logf(se) + mm;
        float ent = 0.f;
#pragma unroll
        for (int q = 0; q < 4; q++) {
            float lp = lg[q] - lse;
            ent -= expf(lp) * lp;
        }
        out[1 * B + b] = lg[mut[b]] - lse;
        out[3 * B + b] = ent;
        out[0 * B + b] = (ls[loc[b]] - m) - logZ;
        out[2 * B + b] = logZ - S / Z;
    }
    if (tid < 32) {
        float h2 = lcb1[tid];
#pragma unroll
        for (int k = 0; k < 32; k++) h2 += poolr[k] * lcw1[k * 32 + tid];
        h2 = fmaxf(h2, 0.f);
        float v = h2 * lcw2[tid];
#pragma unroll
        for (int o = 16; o > 0; o >>= 1) v += __shfl_down_sync(0xffffffffu, v, o);
        if (tid == 0) out[4 * B + b] = v + lcb2[0];
        float h3 = mcb1[tid];
#pragma unroll
        for (int k = 0; k < 32; k++) h3 += selr[k] * mcw1[k * 32 + tid];
        h3 = fmaxf(h3, 0.f);
        float v2 = h3 * mcw2[tid];
#pragma unroll
        for (int o = 16; o > 0; o >>= 1) v2 += __shfl_down_sync(0xffffffffu, v2, o);
        if (tid == 0) out[5 * B + b] = v2 + mcb2[0];
    }
}

extern "C" void kernel_launch(void* const* d_in, const int* in_sizes, int n_in,
                              void* d_out, int out_size) {
    const float* x      = (const float*)d_in[0];
    const float* eattr  = (const float*)d_in[1];
    const int*   ei     = (const int*)d_in[2];
    const int*   ptr    = (const int*)d_in[4];
    const int*   loc    = (const int*)d_in[5];
    const int*   mut    = (const int*)d_in[6];
    const float* w_in   = (const float*)d_in[7];
    const float* b_in   = (const float*)d_in[8];
    const float* w_self = (const float*)d_in[9];
    const float* w_nb   = (const float*)d_in[10];
    const float* w_edge = (const float*)d_in[11];
    const float* b_l    = (const float*)d_in[12];
    const float* w_out  = (const float*)d_in[13];
    const float* b_out  = (const float*)d_in[14];
    const float* la_w1  = (const float*)d_in[15];
    const float* la_b1  = (const float*)d_in[16];
    const float* la_w2  = (const float*)d_in[17];
    const float* la_b2  = (const float*)d_in[18];
    const float* ma_w1  = (const float*)d_in[19];
    const float* ma_b1  = (const float*)d_in[20];
    const float* ma_w2  = (const float*)d_in[21];
    const float* ma_b2  = (const float*)d_in[22];
    const float* lc_w1  = (const float*)d_in[23];
    const float* lc_b1  = (const float*)d_in[24];
    const float* lc_w2  = (const float*)d_in[25];
    const float* lc_b2  = (const float*)d_in[26];
    const float* mc_w1  = (const float*)d_in[27];
    const float* mc_b1  = (const float*)d_in[28];
    const float* mc_w2  = (const float*)d_in[29];
    const float* mc_b2  = (const float*)d_in[30];
    float* out = (float*)d_out;

    int N = in_sizes[0] / 8;
    int B = in_sizes[4] - 1;
    const int* src = ei;  // edge_index row 0

    float *hA, *hB, *gA, *gB, *embp, *lg;
    cudaGetSymbolAddress((void**)&hA, g_bufA);
    cudaGetSymbolAddress((void**)&hB, g_bufB);
    cudaGetSymbolAddress((void**)&gA, g_gA);
    cudaGetSymbolAddress((void**)&gB, g_gB);
    cudaGetSymbolAddress((void**)&embp, g_embv);
    cudaGetSymbolAddress((void**)&lg, g_logit);

    cudaFuncSetAttribute(k_in_g, cudaFuncAttributeMaxDynamicSharedMemorySize, SM_IN_G);
    cudaFuncSetAttribute(k_layer_f, cudaFuncAttributeMaxDynamicSharedMemorySize, SM_LAYER);
    cudaFuncSetAttribute(k_l2, cudaFuncAttributeMaxDynamicSharedMemorySize, SM_L2);

    int gb = (N + 127) / 128;
    k_in_g<<<gb, 256, SM_IN_G>>>(x, w_in, b_in, w_nb, hA, gA, N);
    k_layer_f<<<gb, 256, SM_LAYER>>>(hA, gA, w_self, w_edge, b_l, src, eattr,
                                     w_nb + 4096, hB, gB, N);
    k_layer_f<<<gb, 256, SM_LAYER>>>(hB, gB, w_self + 4096, w_edge + 256, b_l + 64, src, eattr,
                                     w_nb + 8192, hA, gA, N);
    k_l2<<<gb, 256, SM_L2>>>(hA, gA, w_self + 8192, w_edge + 512, b_l + 128, src, eattr,
                             w_out, b_out, la_w1, la_b1, la_w2, la_b2, embp, lg, N);
    k_heads<<<B, 256>>>(embp, lg, ptr, loc, mut,
                        ma_w1, ma_b1, ma_w2, ma_b2,
                        lc_w1, lc_b1, lc_w2, lc_b2,
                        mc_w1, mc_b1, mc_w2, mc_b2,
                        out, B);
}

// round 11
// speedup vs baseline: 1.2009x; 1.2009x over previous
#include <cuda_runtime.h>
#include <math.h>

#define NMAX 393216   // 768 * 512 upper bound on total nodes
#define AT_S 134      // transposed tile stride (even for 8B ull loads)

typedef unsigned long long ull;

// scratch (allocation-free rule: device globals)
__device__ float g_bufA[NMAX * 64];
__device__ float g_bufB[NMAX * 64];
__device__ float g_gA[NMAX * 64];
__device__ float g_gB[NMAX * 64];
__device__ float g_embv[NMAX * 32];
__device__ float g_logit[NMAX];

// dynamic smem layout (bytes)
#define OFF_WS   34304                    // at = 64*134*4
#define OFF_WES  (OFF_WS + 16384)         // ws[4096]
#define OFF_BS   (OFF_WES + 1024)         // wes[256]
#define SM_LAYER (OFF_BS + 256)           // bs[64]
#define SM_L2    (SM_LAYER + 128)         // + bos[32]
#define SM_IN_G  (OFF_WES + 4608 + 256)   // xs[128][9] + bs[64]

// packed fp32x2 helpers (Blackwell)
#define FFMA2(d, a, b) asm("fma.rn.f32x2 %0, %1, %2, %0;" : "+l"(d) : "l"(a), "l"(b))
#define PACKF2(d, x)   asm("mov.b64 %0, {%1, %1};" : "=l"(d) : "f"(x))
#define UNPACK2(lo, hi, p) asm("mov.b64 {%0, %1}, %2;" : "=f"(lo), "=f"(hi) : "l"(p))

// ---- 128x64x64 mma by 256 threads: 8 rows x 4 cols/thread, rowpair f32x2 ----
__device__ __forceinline__ void mma64_4(const float (*at)[AT_S], const float* __restrict__ ws,
                                        int r0, int c0, ull acc[4][4]) {
#pragma unroll
    for (int p = 0; p < 4; p++)
#pragma unroll
        for (int c = 0; c < 4; c++) acc[p][c] = 0ULL;
#pragma unroll 8
    for (int k = 0; k < 64; k++) {
        const ull* ap = (const ull*)&at[k][r0];
        ull a0 = ap[0], a1 = ap[1], a2 = ap[2], a3 = ap[3];
        float4 wA = *(const float4*)&ws[k * 64 + c0];
        ull w0, w1, w2, w3;
        PACKF2(w0, wA.x); PACKF2(w1, wA.y); PACKF2(w2, wA.z); PACKF2(w3, wA.w);
        FFMA2(acc[0][0], a0, w0); FFMA2(acc[0][1], a0, w1);
        FFMA2(acc[0][2], a0, w2); FFMA2(acc[0][3], a0, w3);
        FFMA2(acc[1][0], a1, w0); FFMA2(acc[1][1], a1, w1);
        FFMA2(acc[1][2], a1, w2); FFMA2(acc[1][3], a1, w3);
        FFMA2(acc[2][0], a2, w0); FFMA2(acc[2][1], a2, w1);
        FFMA2(acc[2][2], a2, w2); FFMA2(acc[2][3], a2, w3);
        FFMA2(acc[3][0], a3, w0); FFMA2(acc[3][1], a3, w1);
        FFMA2(acc[3][2], a3, w2); FFMA2(acc[3][3], a3, w3);
    }
}

// ---- 128x32x64 mma by 256 threads: 8 rows x 2 cols/thread (ws stride 32) ----
__device__ __forceinline__ void mma32_2(const float (*at)[AT_S], const float* __restrict__ ws,
                                        int r0, int c0, ull acc[4][2]) {
#pragma unroll
    for (int p = 0; p < 4; p++)
#pragma unroll
        for (int c = 0; c < 2; c++) acc[p][c] = 0ULL;
#pragma unroll 8
    for (int k = 0; k < 64; k++) {
        const ull* ap = (const ull*)&at[k][r0];
        ull a0 = ap[0], a1 = ap[1], a2 = ap[2], a3 = ap[3];
        float2 wA = *(const float2*)&ws[k * 32 + c0];
        ull w0, w1;
        PACKF2(w0, wA.x); PACKF2(w1, wA.y);
        FFMA2(acc[0][0], a0, w0); FFMA2(acc[0][1], a0, w1);
        FFMA2(acc[1][0], a1, w0); FFMA2(acc[1][1], a1, w1);
        FFMA2(acc[2][0], a2, w0); FFMA2(acc[2][1], a2, w1);
        FFMA2(acc[3][0], a3, w0); FFMA2(acc[3][1], a3, w1);
    }
}

// ---- stage a 128x64 tile transposed into at[k][row], 256 threads ----
__device__ __forceinline__ void stage_tile(const float* __restrict__ A, int i0, int N,
                                           float (*at)[AT_S], int tid) {
    int lrow = tid >> 1;
    int q0 = (tid & 1) * 8;
    int i = i0 + lrow;
    const float4* A4 = (const float4*)A;
#pragma unroll
    for (int q = 0; q < 8; q++) {
        float4 v = (i < N) ? A4[(size_t)i * 16 + q0 + q] : make_float4(0.f, 0.f, 0.f, 0.f);
        int kb = (q0 + q) * 4;
        at[kb + 0][lrow] = v.x;
        at[kb + 1][lrow] = v.y;
        at[kb + 2][lrow] = v.z;
        at[kb + 3][lrow] = v.w;
    }
}

// ---- per-thread gather+combine for one row, 4 cols [c0,c0+4) ----
// returns o4 = relu(gemm + agg + b) for cols c0..c0+3
__device__ __forceinline__ float4 combine_row(const float* __restrict__ G,
                                              const int* __restrict__ src,
                                              const float* __restrict__ ea,
                                              const float4 wer[4], const float4 b4,
                                              int i, int c0, float v0, float v1,
                                              float v2, float v3) {
    int4 s4 = *(const int4*)&src[4 * i];
    int ss[4] = {s4.x, s4.y, s4.z, s4.w};
    const float4* eap = (const float4*)&ea[(size_t)16 * i];
    float ax = 0.f, ay = 0.f, az = 0.f, aw = 0.f;
#pragma unroll
    for (int e = 0; e < 4; e++) {
        float4 m = *(const float4*)&G[(size_t)ss[e] * 64 + c0];
        float4 e4 = eap[e];
        m.x += e4.x * wer[0].x + e4.y * wer[1].x + e4.z * wer[2].x + e4.w * wer[3].x;
        m.y += e4.x * wer[0].y + e4.y * wer[1].y + e4.z * wer[2].y + e4.w * wer[3].y;
        m.z += e4.x * wer[0].z + e4.y * wer[1].z + e4.z * wer[2].z + e4.w * wer[3].z;
        m.w += e4.x * wer[0].w + e4.y * wer[1].w + e4.z * wer[2].w + e4.w * wer[3].w;
        ax += fmaxf(m.x, 0.f); ay += fmaxf(m.y, 0.f);
        az += fmaxf(m.z, 0.f); aw += fmaxf(m.w, 0.f);
    }
    float4 o;
    o.x = fmaxf(v0 + ax + b4.x, 0.f);
    o.y = fmaxf(v1 + ay + b4.y, 0.f);
    o.z = fmaxf(v2 + az + b4.z, 0.f);
    o.w = fmaxf(v3 + aw + b4.w, 0.f);
    return o;
}

// =============== k_in_g: h0 = relu(x@w_in+b); G0 = h0 @ w_nb[0] ===============
__global__ void __launch_bounds__(256, 3) k_in_g(const float* __restrict__ x,
                                                 const float* __restrict__ w_in,
                                                 const float* __restrict__ b_in,
                                                 const float* __restrict__ wnb0,
                                                 float* __restrict__ H0,
                                                 float* __restrict__ G0, int N) {
    extern __shared__ __align__(16) char sm[];
    float (*at)[AT_S] = (float (*)[AT_S])sm;
    float* ws = (float*)(sm + OFF_WS);
    float (*xs)[9] = (float (*)[9])(sm + OFF_WES);
    float* bs = (float*)(sm + OFF_WES + 4608);
    int tid = threadIdx.x;
    int i0 = blockIdx.x * 128;
    for (int t = tid; t < 512; t += 256) ws[t] = w_in[t];
    if (tid < 64) bs[tid] = b_in[tid];
    if (tid < 128) {
        int i = i0 + tid;
        float4 v0, v1;
        if (i < N) { v0 = ((const float4*)x)[i * 2]; v1 = ((const float4*)x)[i * 2 + 1]; }
        else { v0 = make_float4(0.f, 0.f, 0.f, 0.f); v1 = v0; }
        xs[tid][0] = v0.x; xs[tid][1] = v0.y; xs[tid][2] = v0.z; xs[tid][3] = v0.w;
        xs[tid][4] = v1.x; xs[tid][5] = v1.y; xs[tid][6] = v1.z; xs[tid][7] = v1.w;
    }
    __syncthreads();
    // input GEMM: 256 threads, 4 rows x 8 cols each
    int tr = tid >> 3, tc = tid & 7;   // tr 0..31
    int r0i = tr * 4, c0 = tc * 8;
    float acc[4][8];
#pragma unroll
    for (int r = 0; r < 4; r++)
#pragma unroll
        for (int c = 0; c < 8; c++) acc[r][c] = bs[c0 + c];
#pragma unroll
    for (int k = 0; k < 8; k++) {
        float w8[8];
#pragma unroll
        for (int c = 0; c < 8; c++) w8[c] = ws[k * 64 + c0 + c];
#pragma unroll
        for (int r = 0; r < 4; r++) {
            float a = xs[r0i + r][k];
#pragma unroll
            for (int c = 0; c < 8; c++) acc[r][c] += a * w8[c];
        }
    }
#pragma unroll
    for (int r = 0; r < 4; r++) {
        int row = r0i + r;
        int i = i0 + row;
#pragma unroll
        for (int c = 0; c < 8; c++) acc[r][c] = fmaxf(acc[r][c], 0.f);
        if (i < N) {
            *(float4*)&H0[(size_t)i * 64 + c0] = make_float4(acc[r][0], acc[r][1], acc[r][2], acc[r][3]);
            *(float4*)&H0[(size_t)i * 64 + c0 + 4] = make_float4(acc[r][4], acc[r][5], acc[r][6], acc[r][7]);
        }
#pragma unroll
        for (int c = 0; c < 8; c++) at[c0 + c][row] = acc[r][c];
    }
    __syncthreads();
    for (int t = tid; t < 4096; t += 256) ws[t] = wnb0[t];
    __syncthreads();
    // G0 GEMM: 256 threads, 8 rows x 4 cols each
    int r0 = (tid >> 4) * 8, c04 = (tid & 15) * 4;
    ull acc2[4][4];
    mma64_4(at, ws, r0, c04, acc2);
#pragma unroll
    for (int p = 0; p < 4; p++) {
        float lo[4], hi[4];
#pragma unroll
        for (int c = 0; c < 4; c++) UNPACK2(lo[c], hi[c], acc2[p][c]);
        int ia = i0 + r0 + 2 * p;
        if (ia < N)
            *(float4*)&G0[(size_t)ia * 64 + c04] = make_float4(lo[0], lo[1], lo[2], lo[3]);
        if (ia + 1 < N)
            *(float4*)&G0[(size_t)(ia + 1) * 64 + c04] = make_float4(hi[0], hi[1], hi[2], hi[3]);
    }
}

// === fused layer: h' = relu(h@wself + b + agg); G' = h' @ wnb_next ===
// relies on dst == repeat(arange(N),4): node i's edges are [4i, 4i+4)
__global__ void __launch_bounds__(256, 3) k_layer_f(const float* __restrict__ H,
                                                    const float* __restrict__ G,
                                                    const float* __restrict__ wself,
                                                    const float* __restrict__ wedge,
                                                    const float* __restrict__ bl,
                                                    const int* __restrict__ src,
                                                    const float* __restrict__ ea,
                                                    const float* __restrict__ wnb_next,
                                                    float* __restrict__ Hout,
                                                    float* __restrict__ Gnext, int N) {
    extern __shared__ __align__(16) char sm[];
    float (*at)[AT_S] = (float (*)[AT_S])sm;
    float* ws = (float*)(sm + OFF_WS);
    float* wes = (float*)(sm + OFF_WES);
    float* bs = (float*)(sm + OFF_BS);
    int tid = threadIdx.x;
    int i0 = blockIdx.x * 128;
    for (int t = tid; t < 4096; t += 256) ws[t] = wself[t];
    if (tid < 256) wes[tid] = wedge[tid];
    if (tid < 64) bs[tid] = bl[tid];
    stage_tile(H, i0, N, at, tid);
    __syncthreads();

    int r0 = (tid >> 4) * 8, c04 = (tid & 15) * 4;
    ull acc[4][4];
    mma64_4(at, ws, r0, c04, acc);
    __syncthreads();   // GEMM1 done reading at/ws

    for (int t = tid; t < 4096; t += 256) ws[t] = wnb_next[t];

    float4 wer[4];
#pragma unroll
    for (int d = 0; d < 4; d++) wer[d] = *(const float4*)&wes[d * 64 + c04];
    float4 b4 = *(const float4*)&bs[c04];

#pragma unroll
    for (int p = 0; p < 4; p++) {
        float v[2][4];
#pragma unroll
        for (int c = 0; c < 4; c++) UNPACK2(v[0][c], v[1][c], acc[p][c]);
#pragma unroll
        for (int rr = 0; rr < 2; rr++) {
            int row = r0 + 2 * p + rr;
            int i = i0 + row;
            if (i < N) {
                float4 o = combine_row(G, src, ea, wer, b4, i, c04,
                                       v[rr][0], v[rr][1], v[rr][2], v[rr][3]);
                *(float4*)&Hout[(size_t)i * 64 + c04] = o;
                at[c04 + 0][row] = o.x;
                at[c04 + 1][row] = o.y;
                at[c04 + 2][row] = o.z;
                at[c04 + 3][row] = o.w;
            }
        }
    }
    __syncthreads();

    ull acc2[4][4];
    mma64_4(at, ws, r0, c04, acc2);
#pragma unroll
    for (int p = 0; p < 4; p++) {
        float lo[4], hi[4];
#pragma unroll
        for (int c = 0; c < 4; c++) UNPACK2(lo[c], hi[c], acc2[p][c]);
        int ia = i0 + r0 + 2 * p;
        if (ia < N)
            *(float4*)&Gnext[(size_t)ia * 64 + c04] = make_float4(lo[0], lo[1], lo[2], lo[3]);
        if (ia + 1 < N)
            *(float4*)&Gnext[(size_t)(ia + 1) * 64 + c04] = make_float4(hi[0], hi[1], hi[2], hi[3]);
    }
}

// === last layer: h3; emb = h3@wout + bout; logit = MLP(emb) ===
__global__ void __launch_bounds__(256, 3) k_l2(const float* __restrict__ H,
                                               const float* __restrict__ G,
                                               const float* __restrict__ wself,
                                               const float* __restrict__ wedge,
                                               const float* __restrict__ bl,
                                               const int* __restrict__ src,
                                               const float* __restrict__ ea,
                                               const float* __restrict__ wout,
                                               const float* __restrict__ bout,
                                               const float* __restrict__ law1,
                                               const float* __restrict__ lab1,
                                               const float* __restrict__ law2,
                                               const float* __restrict__ lab2,
                                               float* __restrict__ emb,
                                               float* __restrict__ logit, int N) {
    extern __shared__ __align__(16) char sm[];
    float (*at)[AT_S] = (float (*)[AT_S])sm;
    float* ws = (float*)(sm + OFF_WS);
    float* wes = (float*)(sm + OFF_WES);
    float* bs = (float*)(sm + OFF_BS);
    float* bos = (float*)(sm + SM_LAYER);
    int tid = threadIdx.x;
    int i0 = blockIdx.x * 128;
    for (int t = tid; t < 4096; t += 256) ws[t] = wself[t];
    if (tid < 256) wes[tid] = wedge[tid];
    if (tid < 64) bs[tid] = bl[tid];
    if (tid < 32) bos[tid] = bout[tid];
    stage_tile(H, i0, N, at, tid);
    __syncthreads();

    int r0 = (tid >> 4) * 8, c04 = (tid & 15) * 4;
    ull acc[4][4];
    mma64_4(at, ws, r0, c04, acc);
    __syncthreads();

    // ws: [0..2047]=wout, [2048..3071]=la_w1, [3072..3103]=la_b1, [3104..3135]=la_w2
    for (int t = tid; t < 2048; t += 256) ws[t] = wout[t];
    for (int t = tid; t < 1024; t += 256) ws[2048 + t] = law1[t];
    if (tid < 32) { ws[3072 + tid] = lab1[tid]; ws[3104 + tid] = law2[tid]; }

    float4 wer[4];
#pragma unroll
    for (int d = 0; d < 4; d++) wer[d] = *(const float4*)&wes[d * 64 + c04];
    float4 b4 = *(const float4*)&bs[c04];

#pragma unroll
    for (int p = 0; p < 4; p++) {
        float v[2][4];
#pragma unroll
        for (int c = 0; c < 4; c++) UNPACK2(v[0][c], v[1][c], acc[p][c]);
#pragma unroll
        for (int rr = 0; rr < 2; rr++) {
            int row = r0 + 2 * p + rr;
            int i = i0 + row;
            if (i < N) {
                float4 o = combine_row(G, src, ea, wer, b4, i, c04,
                                       v[rr][0], v[rr][1], v[rr][2], v[rr][3]);
                at[c04 + 0][row] = o.x;
                at[c04 + 1][row] = o.y;
                at[c04 + 2][row] = o.z;
                at[c04 + 3][row] = o.w;
            }
        }
    }
    __syncthreads();

    // emb GEMM: 256 threads, 8 rows x 2 cols each
    int c02 = (tid & 15) * 2;
    ull acc2[4][2];
    mma32_2(at, ws, r0, c02, acc2);
    __syncthreads();   // everyone done reading at -> reuse as em[row*33+c]

    float* em = &at[0][0];
#pragma unroll
    for (int p = 0; p < 4; p++) {
        float lo[2], hi[2];
        UNPACK2(lo[0], hi[0], acc2[p][0]);
        UNPACK2(lo[1], hi[1], acc2[p][1]);
        lo[0] += bos[c02]; lo[1] += bos[c02 + 1];
        hi[0] += bos[c02]; hi[1] += bos[c02 + 1];
        int rowa = r0 + 2 * p;
        int ia = i0 + rowa;
        if (ia < N)
            *(float2*)&emb[(size_t)ia * 32 + c02] = make_float2(lo[0], lo[1]);
        if (ia + 1 < N)
            *(float2*)&emb[(size_t)(ia + 1) * 32 + c02] = make_float2(hi[0], hi[1]);
        em[rowa * 33 + c02] = lo[0];
        em[rowa * 33 + c02 + 1] = lo[1];
        em[(rowa + 1) * 33 + c02] = hi[0];
        em[(rowa + 1) * 33 + c02 + 1] = hi[1];
    }
    __syncthreads();

    // per-node location logit MLP: two threads per row, split over output j
    {
        int row = tid >> 1;
        int half = tid & 1;
        int i = i0 + row;
        float vsum = 0.f;
        if (i < N) {
            float er[32];
#pragma unroll
            for (int k = 0; k < 32; k++) er[k] = em[row * 33 + k];
#pragma unroll 4
            for (int jj = 0; jj < 16; jj++) {
                int j = half * 16 + jj;
                float s = ws[3072 + j];
#pragma unroll
                for (int k = 0; k < 32; k++) s += er[k] * ws[2048 + k * 32 + j];
                vsum += fmaxf(s, 0.f) * ws[3104 + j];
            }
        }
        vsum += __shfl_xor_sync(0xffffffffu, vsum, 1);
        if (half == 0 && i < N) logit[i] = vsum + lab2[0];
    }
}

// -------- per-graph heads: one block per graph --------
__global__ void k_heads(const float* __restrict__ emb, const float* __restrict__ logit,
                        const int* __restrict__ ptr, const int* __restrict__ loc,
                        const int* __restrict__ mut,
                        const float* __restrict__ maw1, const float* __restrict__ mab1,
                        const float* __restrict__ maw2, const float* __restrict__ mab2,
                        const float* __restrict__ lcw1, const float* __restrict__ lcb1,
                        const float* __restrict__ lcw2, const float* __restrict__ lcb2,
                        const float* __restrict__ mcw1, const float* __restrict__ mcb1,
                        const float* __restrict__ mcw2, const float* __restrict__ mcb2,
                        float* __restrict__ out, int B) {
    __shared__ float ls[768];
    __shared__ float red[256];
    __shared__ float red2[256];
    __shared__ float pool[8][33];
    __shared__ float poolr[32];
    __shared__ float selr[32];
    __shared__ float hidm[32];
    int b = blockIdx.x, tid = threadIdx.x;
    int i0 = ptr[b], i1 = ptr[b + 1];
    int cnt = i1 - i0;
    for (int t = tid; t < cnt; t += 256) ls[t] = logit[i0 + t];
    int j = tid & 31, r = tid >> 5;
    float p = 0.f;
    for (int t = r; t < cnt; t += 8) p += emb[(size_t)(i0 + t) * 32 + j];
    pool[r][j] = p;
    __syncthreads();
    if (tid < 32) {
        float s = 0.f;
#pragma unroll
        for (int rr = 0; rr < 8; rr++) s += pool[rr][tid];
        poolr[tid] = s;
    }
    float m = -1e30f;
    for (int t = tid; t < cnt; t += 256) m = fmaxf(m, ls[t]);
    red[tid] = m;
    __syncthreads();
    for (int s = 128; s > 0; s >>= 1) {
        if (tid < s) red[tid] = fmaxf(red[tid], red[tid + s]);
        __syncthreads();
    }
    m = red[0];
    __syncthreads();
    float z = 0.f, sz = 0.f;
    for (int t = tid; t < cnt; t += 256) {
        float zz = ls[t] - m;
        float e = expf(zz);
        z += e; sz += e * zz;
    }
    red[tid] = z; red2[tid] = sz;
    __syncthreads();
    for (int s = 128; s > 0; s >>= 1) {
        if (tid < s) { red[tid] += red[tid + s]; red2[tid] += red2[tid + s]; }
        __syncthreads();
    }
    float Z = red[0], S = red2[0];
    float logZ = logf(Z);
    int gl = i0 + loc[b];
    if (tid < 32) selr[tid] = emb[(size_t)gl * 32 + tid];
    __syncthreads();
    if (tid < 32) {
        float h1 = mab1[tid];
#pragma unroll
        for (int k = 0; k < 32; k++) h1 += selr[k] * maw1[k * 32 + tid];
        hidm[tid] = fmaxf(h1, 0.f);
    }
    __syncthreads();
    if (tid == 0) {
        float lg[4];
        float mm = -1e30f;
#pragma unroll
        for (int q = 0; q < 4; q++) {
            float s = mab2[q];
            for (int k = 0; k < 32; k++) s += hidm[k] * maw2[k * 4 + q];
            lg[q] = s; mm = fmaxf(mm, s);
        }
        float se = 0.f;
#pragma unroll
        for (int q = 0; q < 4; q++) se += expf(lg[q] - mm);
        float lse = logf(se) + mm;
        float ent = 0.f;
#pragma unroll
        for (int q = 0; q < 4; q++) {
            float lp = lg[q] - lse;
            ent -= expf(lp) * lp;
        }
        out[1 * B + b] = lg[mut[b]] - lse;
        out[3 * B + b] = ent;
        out[0 * B + b] = (ls[loc[b]] - m) - logZ;
        out[2 * B + b] = logZ - S / Z;
    }
    if (tid < 32) {
        float h2 = lcb1[tid];
#pragma unroll
        for (int k = 0; k < 32; k++) h2 += poolr[k] * lcw1[k * 32 + tid];
        h2 = fmaxf(h2, 0.f);
        float v = h2 * lcw2[tid];
#pragma unroll
        for (int o = 16; o > 0; o >>= 1) v += __shfl_down_sync(0xffffffffu, v, o);
        if (tid == 0) out[4 * B + b] = v + lcb2[0];
        float h3 = mcb1[tid];
#pragma unroll
        for (int k = 0; k < 32; k++) h3 += selr[k] * mcw1[k * 32 + tid];
        h3 = fmaxf(h3, 0.f);
        float v2 = h3 * mcw2[tid];
#pragma unroll
        for (int o = 16; o > 0; o >>= 1) v2 += __shfl_down_sync(0xffffffffu, v2, o);
        if (tid == 0) out[5 * B + b] = v2 + mcb2[0];
    }
}

extern "C" void kernel_launch(void* const* d_in, const int* in_sizes, int n_in,
                              void* d_out, int out_size) {
    const float* x      = (const float*)d_in[0];
    const float* eattr  = (const float*)d_in[1];
    const int*   ei     = (const int*)d_in[2];
    const int*   ptr    = (const int*)d_in[4];
    const int*   loc    = (const int*)d_in[5];
    const int*   mut    = (const int*)d_in[6];
    const float* w_in   = (const float*)d_in[7];
    const float* b_in   = (const float*)d_in[8];
    const float* w_self = (const float*)d_in[9];
    const float* w_nb   = (const float*)d_in[10];
    const float* w_edge = (const float*)d_in[11];
    const float* b_l    = (const float*)d_in[12];
    const float* w_out  = (const float*)d_in[13];
    const float* b_out  = (const float*)d_in[14];
    const float* la_w1  = (const float*)d_in[15];
    const float* la_b1  = (const float*)d_in[16];
    const float* la_w2  = (const float*)d_in[17];
    const float* la_b2  = (const float*)d_in[18];
    const float* ma_w1  = (const float*)d_in[19];
    const float* ma_b1  = (const float*)d_in[20];
    const float* ma_w2  = (const float*)d_in[21];
    const float* ma_b2  = (const float*)d_in[22];
    const float* lc_w1  = (const float*)d_in[23];
    const float* lc_b1  = (const float*)d_in[24];
    const float* lc_w2  = (const float*)d_in[25];
    const float* lc_b2  = (const float*)d_in[26];
    const float* mc_w1  = (const float*)d_in[27];
    const float* mc_b1  = (const float*)d_in[28];
    const float* mc_w2  = (const float*)d_in[29];
    const float* mc_b2  = (const float*)d_in[30];
    float* out = (float*)d_out;

    int N = in_sizes[0] / 8;
    int B = in_sizes[4] - 1;
    const int* src = ei;  // edge_index row 0

    float *hA, *hB, *gA, *gB, *embp, *lg;
    cudaGetSymbolAddress((void**)&hA, g_bufA);
    cudaGetSymbolAddress((void**)&hB, g_bufB);
    cudaGetSymbolAddress((void**)&gA, g_gA);
    cudaGetSymbolAddress((void**)&gB, g_gB);
    cudaGetSymbolAddress((void**)&embp, g_embv);
    cudaGetSymbolAddress((void**)&lg, g_logit);

    cudaFuncSetAttribute(k_in_g, cudaFuncAttributeMaxDynamicSharedMemorySize, SM_IN_G);
    cudaFuncSetAttribute(k_layer_f, cudaFuncAttributeMaxDynamicSharedMemorySize, SM_LAYER);
    cudaFuncSetAttribute(k_l2, cudaFuncAttributeMaxDynamicSharedMemorySize, SM_L2);

    int gb = (N + 127) / 128;
    k_in_g<<<gb, 256, SM_IN_G>>>(x, w_in, b_in, w_nb, hA, gA, N);
    k_layer_f<<<gb, 256, SM_LAYER>>>(hA, gA, w_self, w_edge, b_l, src, eattr,
                                     w_nb + 4096, hB, gB, N);
    k_layer_f<<<gb, 256, SM_LAYER>>>(hB, gB, w_self + 4096, w_edge + 256, b_l + 64, src, eattr,
                                     w_nb + 8192, hA, gA, N);
    k_l2<<<gb, 256, SM_L2>>>(hA, gA, w_self + 8192, w_edge + 512, b_l + 128, src, eattr,
                             w_out, b_out, la_w1, la_b1, la_w2, la_b2, embp, lg, N);
    k_heads<<<B, 256>>>(embp, lg, ptr, loc, mut,
                        ma_w1, ma_b1, ma_w2, ma_b2,
                        lc_w1, lc_b1, lc_w2, lc_b2,
                        mc_w1, mc_b1, mc_w2, mc_b2,
                        out, B);
}